// round 3
// baseline (speedup 1.0000x reference)
#include <cuda_runtime.h>
#include <cuda_bf16.h>

// Conv4d: x[4,20,20,40,40,8] (*) k[3,3,3,3,8,16] + bias -> out[4,18,18,38,38,16]
// R2 (resubmit; prior bench was an infra failure): input rows staged through
// SMEM (coalesced), weights via warp-uniform L1-resident LDG.128, math in
// packed fma.rn.f32x2.
// Block = 256 threads = 13 ho-rows x 19 w-chunks (OUTW=2) for one (b,to,zo).

#define THREADS 256
#define HBMAX   13

// ---- problem shape ----
#define B_   4
#define TI   20
#define ZI   20
#define HI   40
#define WI   40
#define CI   8
#define TO   18
#define ZO   18
#define HO   38
#define WO   38
#define CO   16
#define WCHUNKS (WO / 2)       // 19
#define HBLKS   3              // ceil(38/13)

// x strides in floats
#define XS_H  (WI * CI)        // 320
#define XS_Z  (HI * XS_H)      // 12800
#define XS_T  (ZI * XS_Z)      // 256000
#define XS_B  (TI * XS_T)      // 5120000

#define ROW_F4 (XS_H / 4)      // 80 float4 per h-row

__device__ __forceinline__ unsigned long long fma2(unsigned long long a,
                                                   unsigned long long b,
                                                   unsigned long long c) {
    unsigned long long d;
    asm("fma.rn.f32x2 %0, %1, %2, %3;" : "=l"(d) : "l"(a), "l"(b), "l"(c));
    return d;
}

__device__ __forceinline__ unsigned long long pack_dup(float v) {
    unsigned long long d;
    unsigned int u = __float_as_uint(v);
    asm("mov.b64 %0, {%1, %1};" : "=l"(d) : "r"(u));
    return d;
}

__device__ __forceinline__ unsigned long long pack2(float lo, float hi) {
    unsigned long long d;
    unsigned int ulo = __float_as_uint(lo), uhi = __float_as_uint(hi);
    asm("mov.b64 %0, {%1, %2};" : "=l"(d) : "r"(ulo), "r"(uhi));
    return d;
}

__global__ void __launch_bounds__(THREADS)
conv4d_kernel(const float* __restrict__ x,
              const float* __restrict__ w,
              const float* __restrict__ bias,
              float* __restrict__ out)
{
    // input slab: (HBMAX+2) h-rows x 40 pos x 8 ci = 15 x 320 floats = 19.2 KB
    __shared__ float4 sx[(HBMAX + 2) * ROW_F4];

    // block -> (b, to, zo, hblk)
    int blk = blockIdx.x;
    int hblk = blk % HBLKS;  blk /= HBLKS;
    int zo   = blk % ZO;     blk /= ZO;
    int to   = blk % TO;     int b = blk / TO;

    int row0 = hblk * HBMAX;
    int HB   = (row0 + HBMAX <= HO) ? HBMAX : (HO - row0);  // 13,13,12
    int rows_in = HB + 2;
    int n4 = rows_in * ROW_F4;

    int tid = threadIdx.x;
    int wc  = tid % WCHUNKS;          // 0..18
    int hr  = tid / WCHUNKS;          // 0..13
    bool active = (hr < HB);
    int ho = row0 + hr;
    int wo = wc * 2;

    const ulonglong2* __restrict__ wg = reinterpret_cast<const ulonglong2*>(w);

    // accumulators: 2 outputs x 8 f32x2 (16 Cout), init = bias
    unsigned long long acc[2][8];
    #pragma unroll
    for (int j = 0; j < 8; j++) {
        unsigned long long bj = pack2(bias[2 * j], bias[2 * j + 1]);
        acc[0][j] = bj;
        acc[1][j] = bj;
    }

    long xoff_base = (long)b * XS_B + (long)to * XS_T + (long)zo * XS_Z + (long)row0 * XS_H;

    #pragma unroll 1
    for (int kt = 0; kt < 3; kt++) {
        #pragma unroll 1
        for (int kz = 0; kz < 3; kz++) {
            __syncthreads();
            // stage contiguous slab: rows row0..row0+rows_in-1 of plane (to+kt, zo+kz)
            const float4* src = reinterpret_cast<const float4*>(
                x + xoff_base + (long)kt * XS_T + (long)kz * XS_Z);
            for (int i = tid; i < n4; i += THREADS) sx[i] = src[i];
            __syncthreads();

            if (active) {
                #pragma unroll 1
                for (int kh = 0; kh < 3; kh++) {
                    const float4* xr = &sx[(hr + kh) * ROW_F4 + wc * 4];

                    // 4 input positions (wo..wo+3) x 8 ci
                    float in2[4][8];
                    #pragma unroll
                    for (int p = 0; p < 4; p++) {
                        float4 a = xr[2 * p];
                        float4 c = xr[2 * p + 1];
                        in2[p][0] = a.x; in2[p][1] = a.y; in2[p][2] = a.z; in2[p][3] = a.w;
                        in2[p][4] = c.x; in2[p][5] = c.y; in2[p][6] = c.z; in2[p][7] = c.w;
                    }

                    int tap3 = ((kt * 3 + kz) * 3 + kh) * 3;  // tap of kw=0
                    #pragma unroll
                    for (int kw = 0; kw < 3; kw++) {
                        const ulonglong2* wp = &wg[(tap3 + kw) * 32];
                        #pragma unroll
                        for (int ci = 0; ci < 8; ci++) {
                            unsigned long long v0 = pack_dup(in2[kw][ci]);
                            unsigned long long v1 = pack_dup(in2[kw + 1][ci]);
                            #pragma unroll
                            for (int j = 0; j < 4; j++) {
                                ulonglong2 W = wp[ci * 4 + j];   // uniform LDG, L1-hit
                                acc[0][2 * j]     = fma2(v0, W.x, acc[0][2 * j]);
                                acc[0][2 * j + 1] = fma2(v0, W.y, acc[0][2 * j + 1]);
                                acc[1][2 * j]     = fma2(v1, W.x, acc[1][2 * j]);
                                acc[1][2 * j + 1] = fma2(v1, W.y, acc[1][2 * j + 1]);
                            }
                        }
                    }
                }
            }
        }
    }

    if (active) {
        int obase = ((((b * TO + to) * ZO + zo) * HO + ho) * WO + wo) * CO;
        #pragma unroll
        for (int o = 0; o < 2; o++) {
            ulonglong2* op = reinterpret_cast<ulonglong2*>(out + obase + o * CO);
            #pragma unroll
            for (int k = 0; k < 4; k++) {
                ulonglong2 v;
                v.x = acc[o][2 * k];
                v.y = acc[o][2 * k + 1];
                op[k] = v;
            }
        }
    }
}

extern "C" void kernel_launch(void* const* d_in, const int* in_sizes, int n_in,
                              void* d_out, int out_size) {
    const float* x    = (const float*)d_in[0];
    const float* w    = (const float*)d_in[1];
    const float* bias = (const float*)d_in[2];
    float* out        = (float*)d_out;

    int blocks = B_ * TO * ZO * HBLKS;  // 3888
    conv4d_kernel<<<blocks, THREADS>>>(x, w, bias, out);
}